// round 9
// baseline (speedup 1.0000x reference)
#include <cuda_runtime.h>

// ---------------- problem constants ----------------
#define N_NODES 50000
#define E_EDGES 800000
#define TE (E_EDGES + N_NODES)
#define IN_CH   128
#define HID2    128
#define OUT_CH  40
#define NEG_SLOPE 0.2f

// ---------------- scratch (device globals; never touched from host) ----------
__device__ float g_h1[(size_t)N_NODES * HID2];
__device__ float g_x2[(size_t)N_NODES * HID2];
__device__ float g_h2[(size_t)N_NODES * OUT_CH];
__device__ float g_as1[N_NODES * 2];
__device__ float g_ad1[N_NODES * 2];
__device__ float g_as2[N_NODES];
__device__ float g_ad2[N_NODES];
__device__ int   g_deg[N_NODES];     // zero at load; re-zeroed by k_scan each call
__device__ int   g_off[N_NODES + 1];
__device__ int   g_cur[N_NODES];
__device__ int   g_csr[TE];
__device__ int   g_is64;

// ---------------- helpers ----------------
__device__ __forceinline__ float warp_sum(float v) {
    #pragma unroll
    for (int o = 16; o; o >>= 1) v += __shfl_xor_sync(0xffffffffu, v, o);
    return v;
}
__device__ __forceinline__ float lrelu(float x) {
    return x >= 0.f ? x : NEG_SLOPE * x;
}
__device__ __forceinline__ int edge_val(const void* ei, size_t idx) {
    if (g_is64) return (int)((const long long*)ei)[idx];
    return ((const int*)ei)[idx];
}
__device__ __forceinline__ unsigned long long pack2(float lo, float hi) {
    unsigned long long r;
    asm("mov.b64 %0, {%1, %2};" : "=l"(r) : "f"(lo), "f"(hi));
    return r;
}
__device__ __forceinline__ void unpack2(unsigned long long v, float& lo, float& hi) {
    asm("mov.b64 {%0, %1}, %2;" : "=f"(lo), "=f"(hi) : "l"(v));
}
#define FFMA2(acc, a, b) \
    asm("fma.rn.f32x2 %0, %1, %2, %0;" : "+l"(acc) : "l"(a), "l"(b))

// ---------------- edge dtype detection ----------------
__global__ void k_detect(const int* __restrict__ ei32, int E) {
    int nz = 0;
    int stride = E / 64;
    for (int k = 0; k < 64; k++)
        nz |= ei32[2 * (size_t)(k * stride) + 1];
    g_is64 = (nz == 0) ? 1 : 0;
}

// ---------------- CSR build ----------------
__global__ void k_hist(const void* __restrict__ ei, int E, int total, int N) {
    int t = blockIdx.x * blockDim.x + threadIdx.x;
    if (t >= total) return;
    int src, dst;
    if (t < E) { src = edge_val(ei, t); dst = edge_val(ei, (size_t)E + t); }
    else       { src = t - E;           dst = t - E; }
    if ((unsigned)dst >= (unsigned)N || (unsigned)src >= (unsigned)N) return;
    atomicAdd(&g_deg[dst], 1);
}
__global__ void k_scan(int N) {   // single block of 1024; also re-zeroes g_deg
    __shared__ int ssum[1024];
    int t = threadIdx.x;
    int chunk = (N + 1023) / 1024;
    int s = t * chunk;
    int e = min(N, s + chunk);
    int sum = 0;
    for (int i = s; i < e; i++) sum += g_deg[i];
    ssum[t] = sum;
    __syncthreads();
    for (int o = 1; o < 1024; o <<= 1) {
        int v = (t >= o) ? ssum[t - o] : 0;
        __syncthreads();
        ssum[t] += v;
        __syncthreads();
    }
    int run = (t > 0) ? ssum[t - 1] : 0;
    for (int i = s; i < e; i++) {
        int d = g_deg[i];
        g_off[i] = run; g_cur[i] = run;
        g_deg[i] = 0;               // restore state for next call
        run += d;
    }
    if (s < N && e == N) g_off[N] = run;
}
__global__ void k_scatter(const void* __restrict__ ei, int E, int total, int N) {
    int t = blockIdx.x * blockDim.x + threadIdx.x;
    if (t >= total) return;
    int src, dst;
    if (t < E) { src = edge_val(ei, t); dst = edge_val(ei, (size_t)E + t); }
    else       { src = t - E;           dst = t - E; }
    if ((unsigned)dst >= (unsigned)N || (unsigned)src >= (unsigned)N) return;
    int pos = atomicAdd(&g_cur[dst], 1);
    g_csr[pos] = src;
}

// ---------------- GEMM1 + att1 fused ----------------
// h1 = x @ W1, plus per-row attention dots. Block: 64 rows x 128 cols,
// 256 threads = (cg 0..31: cols {cg,cg+32,cg+64,cg+96}) x (rg 0..7: 16 rows).
// x transposed in smem (broadcast LDS.64 row-pairs), packed f32x2 FMA.
#define XT_PAD 66
#define HS_PAD 132   // multiple of 4 -> float4 accesses stay 16B-aligned
__global__ void __launch_bounds__(256, 2)
k_gemm1_att1(const float* __restrict__ x, const float* __restrict__ W,
             const float* __restrict__ att_src, const float* __restrict__ att_dst,
             int N) {
    extern __shared__ float sm[];
    float* Xt = sm;                       // [128][XT_PAD] transposed x (33.8KB)
    float* Ws = sm + 128 * XT_PAD;        // [128][128] W (64KB)
    float* Hs = sm;                       // epilogue alias: [64][HS_PAD], 64*132==128*66

    int tid = threadIdx.x;
    int nb = blockIdx.x * 64;

    // load W (coalesced float4)
    for (int i = tid; i < 128 * 32; i += 256)
        *(float4*)(Ws + 4 * i) = ((const float4*)W)[i];
    // load x transposed: i -> (k4 = i>>6, r = i&63); lanes vary r -> STS conflict-free
    for (int i = tid; i < 32 * 64; i += 256) {
        int k4 = i >> 6, r = i & 63;
        float4 v = (nb + r < N) ? *(const float4*)(x + (size_t)(nb + r) * 128 + 4 * k4)
                                : make_float4(0.f, 0.f, 0.f, 0.f);
        Xt[(4 * k4 + 0) * XT_PAD + r] = v.x;
        Xt[(4 * k4 + 1) * XT_PAD + r] = v.y;
        Xt[(4 * k4 + 2) * XT_PAD + r] = v.z;
        Xt[(4 * k4 + 3) * XT_PAD + r] = v.w;
    }
    __syncthreads();

    int cg = tid & 31;          // lane == cg -> conflict-free W loads
    int rg = tid >> 5;          // rows rg*16 .. rg*16+15 (whole warp same rg -> broadcast x)

    unsigned long long acc[4][8];
    #pragma unroll
    for (int j = 0; j < 4; j++)
        #pragma unroll
        for (int p = 0; p < 8; p++) acc[j][p] = 0ull;

    #pragma unroll 2
    for (int k = 0; k < 128; k++) {
        const float* xrow = Xt + k * XT_PAD + rg * 16;
        unsigned long long xp[8];
        #pragma unroll
        for (int p = 0; p < 8; p++)
            xp[p] = *(const unsigned long long*)(xrow + 2 * p);
        const float* wk = Ws + k * 128 + cg;
        #pragma unroll
        for (int j = 0; j < 4; j++) {
            float w = wk[32 * j];
            unsigned long long wd = pack2(w, w);
            #pragma unroll
            for (int p = 0; p < 8; p++) FFMA2(acc[j][p], xp[p], wd);
        }
    }
    __syncthreads();   // done with Xt; alias as Hs

    // stage results to smem (strided cols -> conflict-free STS; lanes vary cg)
    #pragma unroll
    for (int j = 0; j < 4; j++) {
        int c = cg + 32 * j;
        #pragma unroll
        for (int p = 0; p < 8; p++) {
            float lo, hi;
            unpack2(acc[j][p], lo, hi);
            Hs[(rg * 16 + 2 * p)     * HS_PAD + c] = lo;
            Hs[(rg * 16 + 2 * p + 1) * HS_PAD + c] = hi;
        }
    }
    __syncthreads();

    // coalesced global store
    for (int i = tid; i < 64 * 32; i += 256) {
        int r = i >> 5, c4 = i & 31;
        if (nb + r < N)
            *(float4*)(g_h1 + (size_t)(nb + r) * 128 + 4 * c4) =
                *(const float4*)(Hs + r * HS_PAD + 4 * c4);
    }

    // fused att1: warp w handles rows w*8..w*8+7
    int lane = tid & 31;
    int wid  = tid >> 5;
    float4 a = *(const float4*)(att_src + 4 * lane);
    float4 d = *(const float4*)(att_dst + 4 * lane);
    #pragma unroll
    for (int t = 0; t < 8; t++) {
        int r = wid * 8 + t;
        float4 h = *(const float4*)(Hs + r * HS_PAD + 4 * lane);
        float as = h.x * a.x + h.y * a.y + h.z * a.z + h.w * a.w;
        float ad = h.x * d.x + h.y * d.y + h.z * d.z + h.w * d.w;
        #pragma unroll
        for (int o = 8; o; o >>= 1) {
            as += __shfl_xor_sync(0xffffffffu, as, o);
            ad += __shfl_xor_sync(0xffffffffu, ad, o);
        }
        float as1v = __shfl_sync(0xffffffffu, as, 16);
        float ad1v = __shfl_sync(0xffffffffu, ad, 16);
        if (lane == 0 && nb + r < N) {
            g_as1[2 * (nb + r)]     = as;  g_as1[2 * (nb + r) + 1] = as1v;
            g_ad1[2 * (nb + r)]     = ad;  g_ad1[2 * (nb + r) + 1] = ad1v;
        }
    }
}

// ---------------- aggregation layer 1 (warp per node, float4 gather) ----------
__global__ void k_agg1(const float* __restrict__ b1, int N) {
    int warp = (blockIdx.x * blockDim.x + threadIdx.x) >> 5;
    int lane = threadIdx.x & 31;
    if (warp >= N) return;
    int n = warp;
    int s = g_off[n], epn = g_off[n + 1];
    float ad0 = g_ad1[2 * n], ad1 = g_ad1[2 * n + 1];
    const float* hbase = g_h1 + 4 * lane;
    bool head0 = (lane < 16);

    float4 acc = make_float4(0.f, 0.f, 0.f, 0.f);
    float den0 = 0.f, den1 = 0.f;

    for (int j0 = s; j0 < epn; j0 += 32) {
        int j = j0 + lane;
        int sc = 0; float w0 = 0.f, w1 = 0.f;
        if (j < epn) {
            sc = g_csr[j];
            float2 as = *(const float2*)(g_as1 + 2 * sc);
            w0 = __expf(lrelu(as.x + ad0));
            w1 = __expf(lrelu(as.y + ad1));
        }
        den0 += w0; den1 += w1;
        int cnt = min(32, epn - j0);
        int i = 0;
        #define STEP(u) {                                                   \
            int   ss = __shfl_sync(0xffffffffu, sc, i + (u));               \
            float wa = __shfl_sync(0xffffffffu, w0, i + (u));               \
            float wb = __shfl_sync(0xffffffffu, w1, i + (u));               \
            float ww = head0 ? wa : wb;                                     \
            float4 v = *(const float4*)(hbase + (size_t)ss * 128);          \
            acc.x += ww * v.x; acc.y += ww * v.y;                           \
            acc.z += ww * v.z; acc.w += ww * v.w; }
        for (; i + 8 <= cnt; i += 8) {
            STEP(0) STEP(1) STEP(2) STEP(3) STEP(4) STEP(5) STEP(6) STEP(7)
        }
        for (; i < cnt; i++) { STEP(0) }
        #undef STEP
    }
    den0 = warp_sum(den0) + 1e-16f;
    den1 = warp_sum(den1) + 1e-16f;
    float den = head0 ? den0 : den1;

    float4 bb = *(const float4*)(b1 + 4 * lane);
    float o0 = acc.x / den + bb.x;
    float o1 = acc.y / den + bb.y;
    float o2 = acc.z / den + bb.z;
    float o3 = acc.w / den + bb.w;
    o0 = o0 > 0.f ? o0 : (__expf(o0) - 1.f);
    o1 = o1 > 0.f ? o1 : (__expf(o1) - 1.f);
    o2 = o2 > 0.f ? o2 : (__expf(o2) - 1.f);
    o3 = o3 > 0.f ? o3 : (__expf(o3) - 1.f);
    *(float4*)(g_x2 + (size_t)n * 128 + 4 * lane) = make_float4(o0, o1, o2, o3);
}

// ---------------- GEMM2 + att2 fused ([50000,128] x [128,40]) -----------------
// 64 nodes/block, 320 threads: (cg 0..9 -> float4 of 4 cols, ty 0..31 -> 2 nodes)
__global__ void k_gemm2_att2(const float* __restrict__ W,
                             const float* __restrict__ att_src,
                             const float* __restrict__ att_dst, int N) {
    __shared__ float xs[64][129];
    __shared__ float sAs[64], sAd[64];
    int tid = threadIdx.x;
    int nb = blockIdx.x * 64;
    const float4* xg = (const float4*)g_x2 + (size_t)nb * 32;
    for (int i = tid; i < 64 * 32; i += 320) {
        int r = i >> 5, c4 = (i & 31) * 4;
        float4 v = (nb + r < N) ? xg[i] : make_float4(0.f, 0.f, 0.f, 0.f);
        xs[r][c4] = v.x; xs[r][c4 + 1] = v.y; xs[r][c4 + 2] = v.z; xs[r][c4 + 3] = v.w;
    }
    if (tid < 64) { sAs[tid] = 0.f; sAd[tid] = 0.f; }
    __syncthreads();
    int cg = tid % 10;
    int ty = tid / 10;
    float4 a0 = make_float4(0.f, 0.f, 0.f, 0.f);
    float4 a1 = make_float4(0.f, 0.f, 0.f, 0.f);
    #pragma unroll 4
    for (int k = 0; k < 128; k++) {
        float4 wv = *(const float4*)(W + k * 40 + 4 * cg);
        float x0 = xs[ty][k], x1 = xs[ty + 32][k];
        a0.x += x0 * wv.x; a0.y += x0 * wv.y; a0.z += x0 * wv.z; a0.w += x0 * wv.w;
        a1.x += x1 * wv.x; a1.y += x1 * wv.y; a1.z += x1 * wv.z; a1.w += x1 * wv.w;
    }
    int n0 = nb + ty, n1 = nb + ty + 32;
    if (n0 < N) *(float4*)(g_h2 + (size_t)n0 * 40 + 4 * cg) = a0;
    if (n1 < N) *(float4*)(g_h2 + (size_t)n1 * 40 + 4 * cg) = a1;

    // fused att2 partial dots -> smem reduction over the 10 col-groups
    float4 av = *(const float4*)(att_src + 4 * cg);
    float4 dv = *(const float4*)(att_dst + 4 * cg);
    atomicAdd(&sAs[ty],      a0.x * av.x + a0.y * av.y + a0.z * av.z + a0.w * av.w);
    atomicAdd(&sAd[ty],      a0.x * dv.x + a0.y * dv.y + a0.z * dv.z + a0.w * dv.w);
    atomicAdd(&sAs[ty + 32], a1.x * av.x + a1.y * av.y + a1.z * av.z + a1.w * av.w);
    atomicAdd(&sAd[ty + 32], a1.x * dv.x + a1.y * dv.y + a1.z * dv.z + a1.w * dv.w);
    __syncthreads();
    if (tid < 64 && nb + tid < N) {
        g_as2[nb + tid] = sAs[tid];
        g_ad2[nb + tid] = sAd[tid];
    }
}

// ---------------- aggregation layer 2 (warp per node, 3 srcs/iter) ------------
__global__ void k_agg2(const float* __restrict__ b2, float* __restrict__ out, int N) {
    int warp = (blockIdx.x * blockDim.x + threadIdx.x) >> 5;
    int lane = threadIdx.x & 31;
    if (warp >= N) return;
    int n = warp;
    int s = g_off[n], epn = g_off[n + 1];
    float adn = g_ad2[n];
    int u = lane / 10;
    int v = lane - u * 10;

    float4 acc = make_float4(0.f, 0.f, 0.f, 0.f);
    float den = 0.f;
    for (int j0 = s; j0 < epn; j0 += 32) {
        int j = j0 + lane;
        int sc = 0; float w = 0.f;
        if (j < epn) {
            sc = g_csr[j];
            w = __expf(lrelu(g_as2[sc] + adn));
        }
        den += w;
        int cnt = min(32, epn - j0);
        for (int i = 0; i < cnt; i += 3) {
            int e = i + u;
            int es = min(e, cnt - 1);
            int   ss = __shfl_sync(0xffffffffu, sc, es);
            float ww = __shfl_sync(0xffffffffu, w,  es);
            if (e < cnt && u < 3) {
                float4 hv = *(const float4*)(g_h2 + (size_t)ss * 40 + 4 * v);
                acc.x += ww * hv.x; acc.y += ww * hv.y;
                acc.z += ww * hv.z; acc.w += ww * hv.w;
            }
        }
    }
    den = warp_sum(den) + 1e-16f;
    float4 t1, t2;
    t1.x = __shfl_down_sync(0xffffffffu, acc.x, 10);
    t1.y = __shfl_down_sync(0xffffffffu, acc.y, 10);
    t1.z = __shfl_down_sync(0xffffffffu, acc.z, 10);
    t1.w = __shfl_down_sync(0xffffffffu, acc.w, 10);
    t2.x = __shfl_down_sync(0xffffffffu, acc.x, 20);
    t2.y = __shfl_down_sync(0xffffffffu, acc.y, 20);
    t2.z = __shfl_down_sync(0xffffffffu, acc.z, 20);
    t2.w = __shfl_down_sync(0xffffffffu, acc.w, 20);
    if (lane < 10) {
        float4 bb = *(const float4*)(b2 + 4 * lane);
        float4 o;
        o.x = (acc.x + t1.x + t2.x) / den + bb.x;
        o.y = (acc.y + t1.y + t2.y) / den + bb.y;
        o.z = (acc.z + t1.z + t2.z) / den + bb.z;
        o.w = (acc.w + t1.w + t2.w) / den + bb.w;
        *(float4*)(out + (size_t)n * 40 + 4 * lane) = o;
    }
}

// ---------------- launch ----------------
extern "C" void kernel_launch(void* const* d_in, const int* in_sizes, int n_in,
                              void* d_out, int out_size) {
    const float* node_feat = (const float*)d_in[0];
    const void*  edge_idx  = d_in[1];
    const float* W1        = (const float*)d_in[2];
    const float* att_src1  = (const float*)d_in[3];
    const float* att_dst1  = (const float*)d_in[4];
    const float* b1        = (const float*)d_in[5];
    const float* W2        = (const float*)d_in[6];
    const float* att_src2  = (const float*)d_in[7];
    const float* att_dst2  = (const float*)d_in[8];
    const float* b2        = (const float*)d_in[9];
    float*       out       = (float*)d_out;

    const int N = in_sizes[0] / IN_CH;     // 50000
    const int E = in_sizes[1] / 2;         // 800000
    const int total = E + N;

    int warpBlocks = (N * 32 + 255) / 256;
    int g1smem = (128 * XT_PAD + 128 * 128) * sizeof(float);   // ~97.8KB

    cudaFuncSetAttribute(k_gemm1_att1,
                         cudaFuncAttributeMaxDynamicSharedMemorySize, g1smem);

    k_detect <<<1, 1>>>((const int*)edge_idx, E);
    k_hist   <<<(total + 255) / 256, 256>>>(edge_idx, E, total, N);
    k_scan   <<<1, 1024>>>(N);
    k_scatter<<<(total + 255) / 256, 256>>>(edge_idx, E, total, N);

    k_gemm1_att1<<<(N + 63) / 64, 256, g1smem>>>(node_feat, W1, att_src1, att_dst1, N);
    k_agg1 <<<warpBlocks, 256>>>(b1, N);

    k_gemm2_att2<<<(N + 63) / 64, 320>>>(W2, att_src2, att_dst2, N);
    k_agg2 <<<warpBlocks, 256>>>(b2, out, N);
}

// round 10
// speedup vs baseline: 1.1497x; 1.1497x over previous
#include <cuda_runtime.h>

// ---------------- problem constants ----------------
#define N_NODES 50000
#define E_EDGES 800000
#define TE (E_EDGES + N_NODES)   // edges + self-loops
#define IN_CH   128
#define HID2    128              // HEADS*HIDDEN = 2*64
#define OUT_CH  40
#define NEG_SLOPE 0.2f

// ---------------- scratch (device globals; NEVER touched from host) ----------
__device__ float g_h1[(size_t)N_NODES * HID2];
__device__ float g_x2[(size_t)N_NODES * HID2];
__device__ float g_h2[(size_t)N_NODES * OUT_CH];
__device__ float g_as1[N_NODES * 2];
__device__ float g_ad1[N_NODES * 2];
__device__ float g_as2[N_NODES];
__device__ float g_ad2[N_NODES];
__device__ int   g_deg[N_NODES];   // zero at load; re-zeroed by k_scan each call
__device__ int   g_off[N_NODES + 1];
__device__ int   g_cur[N_NODES];
__device__ int   g_csr[TE];
__device__ int   g_is64;

// ---------------- helpers ----------------
__device__ __forceinline__ float warp_sum(float v) {
    #pragma unroll
    for (int o = 16; o; o >>= 1) v += __shfl_xor_sync(0xffffffffu, v, o);
    return v;
}
__device__ __forceinline__ float lrelu(float x) {
    return x >= 0.f ? x : NEG_SLOPE * x;
}
__device__ __forceinline__ int edge_val(const void* ei, size_t idx) {
    if (g_is64) return (int)((const long long*)ei)[idx];
    return ((const int*)ei)[idx];
}
__device__ __forceinline__ unsigned long long pack2(float lo, float hi) {
    unsigned long long r;
    asm("mov.b64 %0, {%1, %2};" : "=l"(r) : "f"(lo), "f"(hi));
    return r;
}
__device__ __forceinline__ void unpack2(unsigned long long v, float& lo, float& hi) {
    asm("mov.b64 {%0, %1}, %2;" : "=f"(lo), "=f"(hi) : "l"(v));
}
#define FFMA2(acc, a, b) \
    asm("fma.rn.f32x2 %0, %1, %2, %0;" : "+l"(acc) : "l"(a), "l"(b))

// ---------------- edge dtype detection ----------------
__global__ void k_detect(const int* __restrict__ ei32, int E) {
    int nz = 0;
    int stride = E / 64;
    for (int k = 0; k < 64; k++)
        nz |= ei32[2 * (size_t)(k * stride) + 1];
    g_is64 = (nz == 0) ? 1 : 0;
}

// ---------------- CSR build ----------------
__global__ void k_hist(const void* __restrict__ ei, int E, int total, int N) {
    int t = blockIdx.x * blockDim.x + threadIdx.x;
    if (t >= total) return;
    int src, dst;
    if (t < E) { src = edge_val(ei, t); dst = edge_val(ei, (size_t)E + t); }
    else       { src = t - E;           dst = t - E; }
    if ((unsigned)dst >= (unsigned)N || (unsigned)src >= (unsigned)N) return;
    atomicAdd(&g_deg[dst], 1);
}
__global__ void k_scan(int N) {   // single block of 1024; also re-zeroes g_deg
    __shared__ int ssum[1024];
    int t = threadIdx.x;
    int chunk = (N + 1023) / 1024;
    int s = t * chunk;
    int e = min(N, s + chunk);
    int sum = 0;
    for (int i = s; i < e; i++) sum += g_deg[i];
    ssum[t] = sum;
    __syncthreads();
    for (int o = 1; o < 1024; o <<= 1) {
        int v = (t >= o) ? ssum[t - o] : 0;
        __syncthreads();
        ssum[t] += v;
        __syncthreads();
    }
    int run = (t > 0) ? ssum[t - 1] : 0;
    for (int i = s; i < e; i++) {
        int d = g_deg[i];
        g_off[i] = run; g_cur[i] = run;
        g_deg[i] = 0;               // restore state for next call
        run += d;
    }
    if (s < N && e == N) g_off[N] = run;
}
__global__ void k_scatter(const void* __restrict__ ei, int E, int total, int N) {
    int t = blockIdx.x * blockDim.x + threadIdx.x;
    if (t >= total) return;
    int src, dst;
    if (t < E) { src = edge_val(ei, t); dst = edge_val(ei, (size_t)E + t); }
    else       { src = t - E;           dst = t - E; }
    if ((unsigned)dst >= (unsigned)N || (unsigned)src >= (unsigned)N) return;
    int pos = atomicAdd(&g_cur[dst], 1);
    g_csr[pos] = src;
}

// ---------------- GEMM1: g_h1 = x @ W1 (FFMA2, de-risked) ---------------------
// 64 rows/block, 256 threads: tid = c(0..31) + 32*rg(0..7).
// Thread: cols 4c..4c+3, rows rg*8..rg*8+7 as 4 packed row-pairs.
// x transposed in smem (broadcast LDS.64 of row-pairs); W from global (L1-hot).
// ~65 regs, 36.9KB smem -> 3 CTAs/SM, no launch_bounds, no spills.
#define G1_PAD 72
__global__ void k_gemm1(const float* __restrict__ x, const float* __restrict__ W,
                        int N) {
    __shared__ float Xt[128][G1_PAD];   // [k][row]
    int tid = threadIdx.x;
    int nb = blockIdx.x * 64;

    // load x transposed: 64 rows x 32 float4 (k4)
    for (int i = tid; i < 64 * 32; i += 256) {
        int r = i & 63, k4 = i >> 6;
        float4 v = (nb + r < N) ? *(const float4*)(x + (size_t)(nb + r) * 128 + 4 * k4)
                                : make_float4(0.f, 0.f, 0.f, 0.f);
        Xt[4 * k4 + 0][r] = v.x;
        Xt[4 * k4 + 1][r] = v.y;
        Xt[4 * k4 + 2][r] = v.z;
        Xt[4 * k4 + 3][r] = v.w;
    }
    __syncthreads();

    int c  = tid & 31;      // col group: cols 4c..4c+3 (lane==c -> coalesced W)
    int rg = tid >> 5;      // rows rg*8..rg*8+7 (whole warp same rg -> broadcast x)

    unsigned long long acc[4][4];   // [rowpair][col]
    #pragma unroll
    for (int p = 0; p < 4; p++)
        #pragma unroll
        for (int j = 0; j < 4; j++) acc[p][j] = 0ull;

    const float* xrow = &Xt[0][rg * 8];
    #pragma unroll 2
    for (int k = 0; k < 128; k++) {
        unsigned long long xp[4];
        #pragma unroll
        for (int p = 0; p < 4; p++)
            xp[p] = *(const unsigned long long*)(xrow + k * G1_PAD + 2 * p);
        float4 wv = __ldg((const float4*)(W + k * 128 + 4 * c));
        unsigned long long w0 = pack2(wv.x, wv.x);
        unsigned long long w1 = pack2(wv.y, wv.y);
        unsigned long long w2 = pack2(wv.z, wv.z);
        unsigned long long w3 = pack2(wv.w, wv.w);
        #pragma unroll
        for (int p = 0; p < 4; p++) {
            FFMA2(acc[p][0], xp[p], w0);
            FFMA2(acc[p][1], xp[p], w1);
            FFMA2(acc[p][2], xp[p], w2);
            FFMA2(acc[p][3], xp[p], w3);
        }
    }

    // stores: per rowpair, build float4 per row over cols 4c..4c+3 (coalesced)
    #pragma unroll
    for (int p = 0; p < 4; p++) {
        float e0, o0, e1, o1, e2, o2, e3, o3;
        unpack2(acc[p][0], e0, o0);
        unpack2(acc[p][1], e1, o1);
        unpack2(acc[p][2], e2, o2);
        unpack2(acc[p][3], e3, o3);
        int r0 = nb + rg * 8 + 2 * p;
        if (r0 < N)
            *(float4*)(g_h1 + (size_t)r0 * 128 + 4 * c) = make_float4(e0, e1, e2, e3);
        if (r0 + 1 < N)
            *(float4*)(g_h1 + (size_t)(r0 + 1) * 128 + 4 * c) = make_float4(o0, o1, o2, o3);
    }
}

// ---------------- attention dots layer 1 (warp per node, float4) --------------
__global__ void k_att1(const float* __restrict__ att_src,
                       const float* __restrict__ att_dst, int N) {
    int warp = (blockIdx.x * blockDim.x + threadIdx.x) >> 5;
    int lane = threadIdx.x & 31;
    if (warp >= N) return;
    float4 h = *(const float4*)(g_h1 + (size_t)warp * 128 + 4 * lane);
    float4 a = *(const float4*)(att_src + 4 * lane);
    float4 d = *(const float4*)(att_dst + 4 * lane);
    float as = h.x * a.x + h.y * a.y + h.z * a.z + h.w * a.w;
    float ad = h.x * d.x + h.y * d.y + h.z * d.z + h.w * d.w;
    #pragma unroll
    for (int o = 8; o; o >>= 1) {
        as += __shfl_xor_sync(0xffffffffu, as, o);
        ad += __shfl_xor_sync(0xffffffffu, ad, o);
    }
    float as1v = __shfl_sync(0xffffffffu, as, 16);
    float ad1v = __shfl_sync(0xffffffffu, ad, 16);
    if (lane == 0) {
        g_as1[2 * warp] = as; g_as1[2 * warp + 1] = as1v;
        g_ad1[2 * warp] = ad; g_ad1[2 * warp + 1] = ad1v;
    }
}

// ---------------- aggregation layer 1 (warp per node, float4 gather) ----------
__global__ void k_agg1(const float* __restrict__ b1, int N) {
    int warp = (blockIdx.x * blockDim.x + threadIdx.x) >> 5;
    int lane = threadIdx.x & 31;
    if (warp >= N) return;
    int n = warp;
    int s = g_off[n], epn = g_off[n + 1];
    float ad0 = g_ad1[2 * n], ad1 = g_ad1[2 * n + 1];
    const float* hbase = g_h1 + 4 * lane;
    bool head0 = (lane < 16);

    float4 acc = make_float4(0.f, 0.f, 0.f, 0.f);
    float den0 = 0.f, den1 = 0.f;

    for (int j0 = s; j0 < epn; j0 += 32) {
        int j = j0 + lane;
        int sc = 0; float w0 = 0.f, w1 = 0.f;
        if (j < epn) {
            sc = g_csr[j];
            float2 as = *(const float2*)(g_as1 + 2 * sc);
            w0 = __expf(lrelu(as.x + ad0));
            w1 = __expf(lrelu(as.y + ad1));
        }
        den0 += w0; den1 += w1;
        int cnt = min(32, epn - j0);
        int i = 0;
        #define STEP(u) {                                                   \
            int   ss = __shfl_sync(0xffffffffu, sc, i + (u));               \
            float wa = __shfl_sync(0xffffffffu, w0, i + (u));               \
            float wb = __shfl_sync(0xffffffffu, w1, i + (u));               \
            float ww = head0 ? wa : wb;                                     \
            float4 v = *(const float4*)(hbase + (size_t)ss * 128);          \
            acc.x += ww * v.x; acc.y += ww * v.y;                           \
            acc.z += ww * v.z; acc.w += ww * v.w; }
        for (; i + 8 <= cnt; i += 8) {
            STEP(0) STEP(1) STEP(2) STEP(3) STEP(4) STEP(5) STEP(6) STEP(7)
        }
        for (; i < cnt; i++) { STEP(0) }
        #undef STEP
    }
    den0 = warp_sum(den0) + 1e-16f;
    den1 = warp_sum(den1) + 1e-16f;
    float den = head0 ? den0 : den1;

    float4 bb = *(const float4*)(b1 + 4 * lane);
    float o0 = acc.x / den + bb.x;
    float o1 = acc.y / den + bb.y;
    float o2 = acc.z / den + bb.z;
    float o3 = acc.w / den + bb.w;
    o0 = o0 > 0.f ? o0 : (__expf(o0) - 1.f);
    o1 = o1 > 0.f ? o1 : (__expf(o1) - 1.f);
    o2 = o2 > 0.f ? o2 : (__expf(o2) - 1.f);
    o3 = o3 > 0.f ? o3 : (__expf(o3) - 1.f);
    *(float4*)(g_x2 + (size_t)n * 128 + 4 * lane) = make_float4(o0, o1, o2, o3);
}

// ---------------- GEMM2: g_h2 = g_x2 @ W2 ([50000,128] x [128,40]) ------------
__global__ void k_gemm2(const float* __restrict__ W, int N) {
    __shared__ float xs[64][129];
    int nb = blockIdx.x * 64;
    const float4* xg = (const float4*)g_x2 + (size_t)nb * 32;
    for (int i = threadIdx.x; i < 64 * 32; i += 320) {
        int r = i >> 5, c4 = (i & 31) * 4;
        float4 v = (nb + r < N) ? xg[i] : make_float4(0.f, 0.f, 0.f, 0.f);
        xs[r][c4] = v.x; xs[r][c4 + 1] = v.y; xs[r][c4 + 2] = v.z; xs[r][c4 + 3] = v.w;
    }
    __syncthreads();
    int cg = threadIdx.x % 10;
    int ty = threadIdx.x / 10;
    float4 a0 = make_float4(0.f, 0.f, 0.f, 0.f);
    float4 a1 = make_float4(0.f, 0.f, 0.f, 0.f);
    #pragma unroll 4
    for (int k = 0; k < 128; k++) {
        float4 wv = *(const float4*)(W + k * 40 + 4 * cg);
        float x0 = xs[ty][k], x1 = xs[ty + 32][k];
        a0.x += x0 * wv.x; a0.y += x0 * wv.y; a0.z += x0 * wv.z; a0.w += x0 * wv.w;
        a1.x += x1 * wv.x; a1.y += x1 * wv.y; a1.z += x1 * wv.z; a1.w += x1 * wv.w;
    }
    int n0 = nb + ty, n1 = nb + ty + 32;
    if (n0 < N) *(float4*)(g_h2 + (size_t)n0 * 40 + 4 * cg) = a0;
    if (n1 < N) *(float4*)(g_h2 + (size_t)n1 * 40 + 4 * cg) = a1;
}

// ---------------- attention dots layer 2 (warp per node, 40 ch) ---------------
__global__ void k_att2(const float* __restrict__ att_src,
                       const float* __restrict__ att_dst, int N) {
    int warp = (blockIdx.x * blockDim.x + threadIdx.x) >> 5;
    int lane = threadIdx.x & 31;
    if (warp >= N) return;
    float as = 0.f, ad = 0.f;
    if (lane < 10) {
        float4 h = *(const float4*)(g_h2 + (size_t)warp * 40 + 4 * lane);
        float4 a = *(const float4*)(att_src + 4 * lane);
        float4 d = *(const float4*)(att_dst + 4 * lane);
        as = h.x * a.x + h.y * a.y + h.z * a.z + h.w * a.w;
        ad = h.x * d.x + h.y * d.y + h.z * d.z + h.w * d.w;
    }
    as = warp_sum(as); ad = warp_sum(ad);
    if (lane == 0) { g_as2[warp] = as; g_ad2[warp] = ad; }
}

// ---------------- aggregation layer 2 (warp per node, 3 srcs/iter) ------------
__global__ void k_agg2(const float* __restrict__ b2, float* __restrict__ out, int N) {
    int warp = (blockIdx.x * blockDim.x + threadIdx.x) >> 5;
    int lane = threadIdx.x & 31;
    if (warp >= N) return;
    int n = warp;
    int s = g_off[n], epn = g_off[n + 1];
    float adn = g_ad2[n];
    int u = lane / 10;
    int v = lane - u * 10;

    float4 acc = make_float4(0.f, 0.f, 0.f, 0.f);
    float den = 0.f;
    for (int j0 = s; j0 < epn; j0 += 32) {
        int j = j0 + lane;
        int sc = 0; float w = 0.f;
        if (j < epn) {
            sc = g_csr[j];
            w = __expf(lrelu(g_as2[sc] + adn));
        }
        den += w;
        int cnt = min(32, epn - j0);
        for (int i = 0; i < cnt; i += 3) {
            int e = i + u;
            int es = min(e, cnt - 1);
            int   ss = __shfl_sync(0xffffffffu, sc, es);
            float ww = __shfl_sync(0xffffffffu, w,  es);
            if (e < cnt && u < 3) {
                float4 hv = *(const float4*)(g_h2 + (size_t)ss * 40 + 4 * v);
                acc.x += ww * hv.x; acc.y += ww * hv.y;
                acc.z += ww * hv.z; acc.w += ww * hv.w;
            }
        }
    }
    den = warp_sum(den) + 1e-16f;
    float4 t1, t2;
    t1.x = __shfl_down_sync(0xffffffffu, acc.x, 10);
    t1.y = __shfl_down_sync(0xffffffffu, acc.y, 10);
    t1.z = __shfl_down_sync(0xffffffffu, acc.z, 10);
    t1.w = __shfl_down_sync(0xffffffffu, acc.w, 10);
    t2.x = __shfl_down_sync(0xffffffffu, acc.x, 20);
    t2.y = __shfl_down_sync(0xffffffffu, acc.y, 20);
    t2.z = __shfl_down_sync(0xffffffffu, acc.z, 20);
    t2.w = __shfl_down_sync(0xffffffffu, acc.w, 20);
    if (lane < 10) {
        float4 bb = *(const float4*)(b2 + 4 * lane);
        float4 o;
        o.x = (acc.x + t1.x + t2.x) / den + bb.x;
        o.y = (acc.y + t1.y + t2.y) / den + bb.y;
        o.z = (acc.z + t1.z + t2.z) / den + bb.z;
        o.w = (acc.w + t1.w + t2.w) / den + bb.w;
        *(float4*)(out + (size_t)n * 40 + 4 * lane) = o;
    }
}

// ---------------- launch ----------------
extern "C" void kernel_launch(void* const* d_in, const int* in_sizes, int n_in,
                              void* d_out, int out_size) {
    const float* node_feat = (const float*)d_in[0];
    const void*  edge_idx  = d_in[1];
    const float* W1        = (const float*)d_in[2];
    const float* att_src1  = (const float*)d_in[3];
    const float* att_dst1  = (const float*)d_in[4];
    const float* b1        = (const float*)d_in[5];
    const float* W2        = (const float*)d_in[6];
    const float* att_src2  = (const float*)d_in[7];
    const float* att_dst2  = (const float*)d_in[8];
    const float* b2        = (const float*)d_in[9];
    float*       out       = (float*)d_out;

    const int N = in_sizes[0] / IN_CH;     // 50000
    const int E = in_sizes[1] / 2;         // 800000
    const int total = E + N;               // 850000

    int warpBlocks = (N * 32 + 255) / 256;

    k_detect <<<1, 1>>>((const int*)edge_idx, E);
    k_hist   <<<(total + 255) / 256, 256>>>(edge_idx, E, total, N);
    k_scan   <<<1, 1024>>>(N);
    k_scatter<<<(total + 255) / 256, 256>>>(edge_idx, E, total, N);

    k_gemm1<<<(N + 63) / 64, 256>>>(node_feat, W1, N);
    k_att1 <<<warpBlocks, 256>>>(att_src1, att_dst1, N);
    k_agg1 <<<warpBlocks, 256>>>(b1, N);

    k_gemm2<<<(N + 63) / 64, 320>>>(W2, N);
    k_att2 <<<warpBlocks, 256>>>(att_src2, att_dst2, N);
    k_agg2 <<<warpBlocks, 256>>>(b2, out, N);
}